// round 2
// baseline (speedup 1.0000x reference)
#include <cuda_runtime.h>

// Problem constants
#define SHIFT   4
#define HEADS   4
#define HDIM    32
#define MTOK    128      // tokens per window (8*8*2)
#define NR      225      // distinct rel-pos indices (15*15)
#define QS      36       // padded row stride (floats) for q/k/v/embed tiles
#define AS      129      // padded row stride (floats) for attn matrix
#define SCALE   0.17677669529663687f   // 32^-0.5

// shared memory layout (in floats)
#define SQ_OFF   0
#define SK_OFF   (MTOK*QS)
#define SV_OFF   (2*MTOK*QS)
#define SQE_OFF  (3*MTOK*QS)
#define SKE_OFF  (SQE_OFF + NR*QS)
#define SVE_OFF  (SKE_OFF + NR*QS)
#define SA_OFF   (SVE_OFF + NR*QS)
#define SMEM_FLOATS (SA_OFF + MTOK*AS)   // 54,636 floats = 218,544 bytes

__global__ __launch_bounds__(256, 1)
void swin_attn_kernel(const float* __restrict__ qkv,
                      const float* __restrict__ mask,
                      const float* __restrict__ rpe,
                      float* __restrict__ out)
{
    extern __shared__ float sm[];
    float* sQ  = sm + SQ_OFF;
    float* sK  = sm + SK_OFF;
    float* sV  = sm + SV_OFF;
    float* sQE = sm + SQE_OFF;   // q_embed slice (pre-scaled)
    float* sKE = sm + SKE_OFF;   // k_embed slice
    float* sVE = sm + SVE_OFF;   // v_embed slice
    float* sA  = sm + SA_OFF;    // attn [128][129]

    const int tid = threadIdx.x;
    const int h   = blockIdx.y;
    const int b   = blockIdx.x >> 8;
    const int win = blockIdx.x & 255;
    const int wi  = win >> 4;
    const int wj  = win & 15;

    // ---- load q,k,v tokens (2 threads per token, 16 floats each) ----
    {
        const int t = tid >> 1, half = tid & 1;
        const int wh = t >> 4, ww = (t >> 1) & 7, n = t & 1;
        const int gy = (wi*8 + wh + SHIFT) & 127;
        const int gx = (wj*8 + ww + SHIFT) & 127;
        const float* base = qkv + (size_t)((((b*128 + gy)*128 + gx)*2 + n)*384) + h*32 + half*16;
        #pragma unroll
        for (int c4 = 0; c4 < 4; c4++) {
            float4 q = ((const float4*)base)[c4];
            float4 k = ((const float4*)(base + 128))[c4];
            float4 v = ((const float4*)(base + 256))[c4];
            q.x *= SCALE; q.y *= SCALE; q.z *= SCALE; q.w *= SCALE;
            *(float4*)(sQ + t*QS + half*16 + c4*4) = q;
            *(float4*)(sK + t*QS + half*16 + c4*4) = k;
            *(float4*)(sV + t*QS + half*16 + c4*4) = v;
        }
    }

    // ---- load 225 rel-pos table rows (q/k/v slices for this head) ----
    // rpe_table row layout is HEAD-MAJOR: [head][q(32)|k(32)|v(32)]
    for (int idx = tid; idx < NR*24; idx += 256) {
        const int r  = idx / 24;
        const int s  = idx % 24;
        const int sl = s >> 3;          // 0=q_embed, 1=k_embed, 2=v_embed
        const int c4 = s & 7;
        float4 v = *(const float4*)(rpe + (size_t)r*384 + h*96 + sl*32 + c4*4);
        float* dst = (sl == 0) ? sQE : (sl == 1) ? sKE : sVE;
        if (sl == 0) { v.x *= SCALE; v.y *= SCALE; v.z *= SCALE; v.w *= SCALE; }
        *(float4*)(dst + r*QS + c4*4) = v;
    }
    __syncthreads();

    // ---- pass 1: qk GEMM (+mask) -> sA, 8x8 register tile per thread ----
    {
        const int ti = tid >> 4, tj = tid & 15;
        float acc[8][8];
        #pragma unroll
        for (int a = 0; a < 8; a++)
            #pragma unroll
            for (int c = 0; c < 8; c++) acc[a][c] = 0.f;

        #pragma unroll
        for (int c4 = 0; c4 < 8; c4++) {
            float4 qv[8], kv[8];
            #pragma unroll
            for (int d = 0; d < 8; d++) qv[d] = *(const float4*)(sQ + (ti + d*16)*QS + c4*4);
            #pragma unroll
            for (int d = 0; d < 8; d++) kv[d] = *(const float4*)(sK + (tj + d*16)*QS + c4*4);
            #pragma unroll
            for (int di = 0; di < 8; di++)
                #pragma unroll
                for (int dj = 0; dj < 8; dj++)
                    acc[di][dj] += qv[di].x*kv[dj].x + qv[di].y*kv[dj].y
                                 + qv[di].z*kv[dj].z + qv[di].w*kv[dj].w;
        }
        const float* mrow = mask + (size_t)win*16384;
        #pragma unroll
        for (int di = 0; di < 8; di++) {
            const int i = ti + di*16;
            #pragma unroll
            for (int dj = 0; dj < 8; dj++) {
                const int j = tj + dj*16;
                sA[i*AS + j] = acc[di][dj] + mrow[i*128 + j];
            }
        }
    }
    __syncthreads();

    // ---- pass 2: qr term: q[i] . k_embed[r(pi,pj)] -> attn[i][2pj],[2pj+1] ----
    {
        const int i   = tid >> 1;
        const int pj0 = (tid & 1) << 5;
        const int phi = i >> 4, pwi = (i >> 1) & 7;
        float4 q[8];
        #pragma unroll
        for (int c4 = 0; c4 < 8; c4++) q[c4] = *(const float4*)(sQ + i*QS + c4*4);
        for (int pj = pj0; pj < pj0 + 32; pj++) {
            const int r = (phi - (pj >> 3) + 7)*15 + (pwi - (pj & 7) + 7);
            float s = 0.f;
            #pragma unroll
            for (int c4 = 0; c4 < 8; c4++) {
                float4 e = *(const float4*)(sKE + r*QS + c4*4);
                s += q[c4].x*e.x + q[c4].y*e.y + q[c4].z*e.z + q[c4].w*e.w;
            }
            sA[i*AS + 2*pj]     += s;
            sA[i*AS + 2*pj + 1] += s;
        }
    }
    __syncthreads();

    // ---- pass 3: kr term: k[j] . q_embed[r(pi,pj)] -> attn[2pi][j],[2pi+1][j] ----
    {
        const int j   = tid >> 1;
        const int pi0 = (tid & 1) << 5;
        const int phj = j >> 4, pwj = (j >> 1) & 7;
        float4 k[8];
        #pragma unroll
        for (int c4 = 0; c4 < 8; c4++) k[c4] = *(const float4*)(sK + j*QS + c4*4);
        for (int pi = pi0; pi < pi0 + 32; pi++) {
            const int r = ((pi >> 3) - phj + 7)*15 + ((pi & 7) - pwj + 7);
            float s = 0.f;
            #pragma unroll
            for (int c4 = 0; c4 < 8; c4++) {
                float4 e = *(const float4*)(sQE + r*QS + c4*4);
                s += k[c4].x*e.x + k[c4].y*e.y + k[c4].z*e.z + k[c4].w*e.w;
            }
            sA[(2*pi)*AS + j]     += s;
            sA[(2*pi + 1)*AS + j] += s;
        }
    }
    __syncthreads();

    // ---- softmax per row (warp per row, 16 rows per warp) ----
    {
        const int w = tid >> 5, l = tid & 31;
        for (int ii = 0; ii < 16; ii++) {
            const int i = w*16 + ii;
            float v[4];
            #pragma unroll
            for (int k = 0; k < 4; k++) v[k] = sA[i*AS + l + 32*k];
            float m = fmaxf(fmaxf(v[0], v[1]), fmaxf(v[2], v[3]));
            #pragma unroll
            for (int off = 16; off; off >>= 1) m = fmaxf(m, __shfl_xor_sync(0xffffffffu, m, off));
            float sum = 0.f;
            #pragma unroll
            for (int k = 0; k < 4; k++) { v[k] = __expf(v[k] - m); sum += v[k]; }
            #pragma unroll
            for (int off = 16; off; off >>= 1) sum += __shfl_xor_sync(0xffffffffu, sum, off);
            const float inv = 1.f / sum;
            #pragma unroll
            for (int k = 0; k < 4; k++) sA[i*AS + l + 32*k] = v[k]*inv;
        }
    }
    __syncthreads();

    // ---- AV + v_embed term + store (warp: 32 rows x 16 channels) ----
    {
        const int w  = tid >> 5, l = tid & 31;
        const int i  = (w & 3)*32 + l;
        const int c0 = (w >> 2)*16;
        const int phi = i >> 4, pwi = (i >> 1) & 7;
        float4 acc[4];
        #pragma unroll
        for (int c4 = 0; c4 < 4; c4++) acc[c4] = make_float4(0.f, 0.f, 0.f, 0.f);

        for (int pj = 0; pj < 64; pj++) {
            const float a0 = sA[i*AS + 2*pj];
            const float a1 = sA[i*AS + 2*pj + 1];
            const float as = a0 + a1;
            const int r = (phi - (pj >> 3) + 7)*15 + (pwi - (pj & 7) + 7);
            const float4* v0 = (const float4*)(sV + (2*pj)*QS + c0);
            const float4* v1 = (const float4*)(sV + (2*pj + 1)*QS + c0);
            const float4* ve = (const float4*)(sVE + r*QS + c0);
            #pragma unroll
            for (int c4 = 0; c4 < 4; c4++) {
                float4 x0 = v0[c4], x1 = v1[c4], xe = ve[c4];
                acc[c4].x += a0*x0.x + a1*x1.x + as*xe.x;
                acc[c4].y += a0*x0.y + a1*x1.y + as*xe.y;
                acc[c4].z += a0*x0.z + a1*x1.z + as*xe.z;
                acc[c4].w += a0*x0.w + a1*x1.w + as*xe.w;
            }
        }
        const int wh = i >> 4, ww = (i >> 1) & 7, n = i & 1;
        const int gy = (wi*8 + wh + SHIFT) & 127;
        const int gx = (wj*8 + ww + SHIFT) & 127;
        float* o = out + (size_t)((((b*128 + gy)*128 + gx)*2 + n)*128) + h*32 + c0;
        #pragma unroll
        for (int c4 = 0; c4 < 4; c4++) ((float4*)o)[c4] = acc[c4];
    }
}

extern "C" void kernel_launch(void* const* d_in, const int* in_sizes, int n_in,
                              void* d_out, int out_size)
{
    const float* qkv  = (const float*)d_in[0];
    const float* mask = (const float*)d_in[1];
    const float* rpe  = (const float*)d_in[2];
    // d_in[3] (rel_pos_index) recomputed on the fly in-kernel

    const size_t smem = SMEM_FLOATS * sizeof(float);
    cudaFuncSetAttribute(swin_attn_kernel,
                         cudaFuncAttributeMaxDynamicSharedMemorySize, (int)smem);
    dim3 grid(1024, HEADS);
    swin_attn_kernel<<<grid, 256, smem>>>(qkv, mask, rpe, (float*)d_out);
}

// round 3
// speedup vs baseline: 1.0290x; 1.0290x over previous
#include <cuda_runtime.h>

// Problem constants
#define SHIFT   4
#define HEADS   4
#define HDIM    32
#define MTOK    128      // tokens per window (8*8*2)
#define NR      225      // distinct rel-pos indices (15*15)
#define QS      36       // padded row stride (floats) for q/k/v/embed tiles
#define AS      130      // padded row stride (floats) for attn matrix (even -> pair-aligned float2)
#define SCALE   0.17677669529663687f   // 32^-0.5

// shared memory layout (in floats)
#define SQ_OFF   0
#define SK_OFF   (MTOK*QS)
#define SV_OFF   (2*MTOK*QS)
#define SQE_OFF  (3*MTOK*QS)
#define SKE_OFF  (SQE_OFF + NR*QS)
#define SVE_OFF  (SKE_OFF + NR*QS)
#define SA_OFF   (SVE_OFF + NR*QS)
#define SMEM_FLOATS (SA_OFF + MTOK*AS)   // 54,764 floats = 219,056 bytes

__global__ __launch_bounds__(256, 1)
void swin_attn_kernel(const float* __restrict__ qkv,
                      const float* __restrict__ mask,
                      const float* __restrict__ rpe,
                      float* __restrict__ out)
{
    extern __shared__ float sm[];
    float* sQ  = sm + SQ_OFF;
    float* sK  = sm + SK_OFF;
    float* sV  = sm + SV_OFF;
    float* sQE = sm + SQE_OFF;   // q_embed slice (pre-scaled)
    float* sKE = sm + SKE_OFF;   // k_embed slice
    float* sVE = sm + SVE_OFF;   // v_embed slice
    float* sA  = sm + SA_OFF;    // attn [128][130]

    const int tid = threadIdx.x;
    const int h   = blockIdx.y;
    const int b   = blockIdx.x >> 8;
    const int win = blockIdx.x & 255;
    const int wi  = win >> 4;
    const int wj  = win & 15;

    // ---- load q,k,v tokens (2 threads per token, 16 floats each) ----
    {
        const int t = tid >> 1, half = tid & 1;
        const int wh = t >> 4, ww = (t >> 1) & 7, n = t & 1;
        const int gy = (wi*8 + wh + SHIFT) & 127;
        const int gx = (wj*8 + ww + SHIFT) & 127;
        const float* base = qkv + (size_t)((((b*128 + gy)*128 + gx)*2 + n)*384) + h*32 + half*16;
        #pragma unroll
        for (int c4 = 0; c4 < 4; c4++) {
            float4 q = ((const float4*)base)[c4];
            float4 k = ((const float4*)(base + 128))[c4];
            float4 v = ((const float4*)(base + 256))[c4];
            q.x *= SCALE; q.y *= SCALE; q.z *= SCALE; q.w *= SCALE;
            *(float4*)(sQ + t*QS + half*16 + c4*4) = q;
            *(float4*)(sK + t*QS + half*16 + c4*4) = k;
            *(float4*)(sV + t*QS + half*16 + c4*4) = v;
        }
    }

    // ---- load 225 rel-pos table rows (q/k/v slices for this head) ----
    // rpe_table row layout is HEAD-MAJOR: [head][q(32)|k(32)|v(32)]
    for (int idx = tid; idx < NR*24; idx += 256) {
        const int r  = idx / 24;
        const int s  = idx % 24;
        const int sl = s >> 3;          // 0=q_embed, 1=k_embed, 2=v_embed
        const int c4 = s & 7;
        float4 v = *(const float4*)(rpe + (size_t)r*384 + h*96 + sl*32 + c4*4);
        float* dst = (sl == 0) ? sQE : (sl == 1) ? sKE : sVE;
        if (sl == 0) { v.x *= SCALE; v.y *= SCALE; v.z *= SCALE; v.w *= SCALE; }
        *(float4*)(dst + r*QS + c4*4) = v;
    }
    __syncthreads();

    // ---- pass 1: qk GEMM (+mask) -> sA, 8x8 register tile per thread ----
    {
        const int ti = tid >> 4, tj = tid & 15;
        float acc[8][8];
        #pragma unroll
        for (int a = 0; a < 8; a++)
            #pragma unroll
            for (int c = 0; c < 8; c++) acc[a][c] = 0.f;

        #pragma unroll
        for (int c4 = 0; c4 < 8; c4++) {
            float4 qv[8], kv[8];
            #pragma unroll
            for (int d = 0; d < 8; d++) qv[d] = *(const float4*)(sQ + (ti + d*16)*QS + c4*4);
            #pragma unroll
            for (int d = 0; d < 8; d++) kv[d] = *(const float4*)(sK + (tj + d*16)*QS + c4*4);
            #pragma unroll
            for (int di = 0; di < 8; di++)
                #pragma unroll
                for (int dj = 0; dj < 8; dj++)
                    acc[di][dj] += qv[di].x*kv[dj].x + qv[di].y*kv[dj].y
                                 + qv[di].z*kv[dj].z + qv[di].w*kv[dj].w;
        }
        const float* mrow = mask + (size_t)win*16384;
        #pragma unroll
        for (int di = 0; di < 8; di++) {
            const int i = ti + di*16;
            #pragma unroll
            for (int dj = 0; dj < 8; dj++) {
                const int j = tj + dj*16;
                sA[i*AS + j] = acc[di][dj] + mrow[i*128 + j];
            }
        }
    }
    __syncthreads();

    // ---- pass 2: qr term. Thread owns row-pixel p (rows 2p,2p+1), 16 pj each.
    //      qr value is identical for columns 2pj and 2pj+1; embed row loaded once per pair.
    {
        const int p   = tid >> 2;
        const int pj0 = (tid & 3) << 4;
        const int phi = p >> 3, pwi = p & 7;
        const int i0  = 2*p;
        float4 q0[8], q1[8];
        #pragma unroll
        for (int c4 = 0; c4 < 8; c4++) {
            q0[c4] = *(const float4*)(sQ + i0*QS + c4*4);
            q1[c4] = *(const float4*)(sQ + (i0+1)*QS + c4*4);
        }
        #pragma unroll 4
        for (int pj = pj0; pj < pj0 + 16; pj++) {
            const int r = (phi - (pj >> 3) + 7)*15 + (pwi - (pj & 7) + 7);
            float s0 = 0.f, s1 = 0.f;
            #pragma unroll
            for (int c4 = 0; c4 < 8; c4++) {
                float4 e = *(const float4*)(sKE + r*QS + c4*4);
                s0 += q0[c4].x*e.x + q0[c4].y*e.y + q0[c4].z*e.z + q0[c4].w*e.w;
                s1 += q1[c4].x*e.x + q1[c4].y*e.y + q1[c4].z*e.z + q1[c4].w*e.w;
            }
            float2* d0 = (float2*)(sA + i0*AS + 2*pj);
            float2* d1 = (float2*)(sA + (i0+1)*AS + 2*pj);
            float2 t0 = *d0, t1 = *d1;
            t0.x += s0; t0.y += s0; *d0 = t0;
            t1.x += s1; t1.y += s1; *d1 = t1;
        }
    }
    __syncthreads();

    // ---- pass 3: kr term. Thread owns col-pixel p (cols 2p,2p+1), 16 pi each.
    //      kr value is identical for rows 2pi and 2pi+1; embed row loaded once per pair.
    {
        const int p   = tid >> 2;
        const int pi0 = (tid & 3) << 4;
        const int phj = p >> 3, pwj = p & 7;
        const int j0  = 2*p;
        float4 k0[8], k1[8];
        #pragma unroll
        for (int c4 = 0; c4 < 8; c4++) {
            k0[c4] = *(const float4*)(sK + j0*QS + c4*4);
            k1[c4] = *(const float4*)(sK + (j0+1)*QS + c4*4);
        }
        #pragma unroll 4
        for (int pi = pi0; pi < pi0 + 16; pi++) {
            const int r = ((pi >> 3) - phj + 7)*15 + ((pi & 7) - pwj + 7);
            float s0 = 0.f, s1 = 0.f;
            #pragma unroll
            for (int c4 = 0; c4 < 8; c4++) {
                float4 e = *(const float4*)(sQE + r*QS + c4*4);
                s0 += k0[c4].x*e.x + k0[c4].y*e.y + k0[c4].z*e.z + k0[c4].w*e.w;
                s1 += k1[c4].x*e.x + k1[c4].y*e.y + k1[c4].z*e.z + k1[c4].w*e.w;
            }
            float2* d0 = (float2*)(sA + (2*pi)*AS + j0);
            float2* d1 = (float2*)(sA + (2*pi+1)*AS + j0);
            float2 t0 = *d0, t1 = *d1;
            t0.x += s0; t0.y += s1; *d0 = t0;
            t1.x += s0; t1.y += s1; *d1 = t1;
        }
    }
    __syncthreads();

    // ---- softmax per row (warp per row, 16 rows per warp) ----
    {
        const int w = tid >> 5, l = tid & 31;
        for (int ii = 0; ii < 16; ii++) {
            const int i = w*16 + ii;
            float v[4];
            #pragma unroll
            for (int k = 0; k < 4; k++) v[k] = sA[i*AS + l + 32*k];
            float m = fmaxf(fmaxf(v[0], v[1]), fmaxf(v[2], v[3]));
            #pragma unroll
            for (int off = 16; off; off >>= 1) m = fmaxf(m, __shfl_xor_sync(0xffffffffu, m, off));
            float sum = 0.f;
            #pragma unroll
            for (int k = 0; k < 4; k++) { v[k] = __expf(v[k] - m); sum += v[k]; }
            #pragma unroll
            for (int off = 16; off; off >>= 1) sum += __shfl_xor_sync(0xffffffffu, sum, off);
            const float inv = 1.f / sum;
            #pragma unroll
            for (int k = 0; k < 4; k++) sA[i*AS + l + 32*k] = v[k]*inv;
        }
    }
    __syncthreads();

    // ---- AV + v_embed term + store.
    //      Thread owns row-pixel p (rows 2p,2p+1) x 8 channels; v/ve rows loaded once per pair.
    {
        const int p   = tid >> 2;
        const int c0  = (tid & 3) << 3;
        const int phi = p >> 3, pwi = p & 7;
        const int i0  = 2*p;
        float4 acc0a = {0,0,0,0}, acc0b = {0,0,0,0};
        float4 acc1a = {0,0,0,0}, acc1b = {0,0,0,0};

        #pragma unroll 4
        for (int pj = 0; pj < 64; pj++) {
            const float2 A0 = *(const float2*)(sA + i0*AS + 2*pj);
            const float2 A1 = *(const float2*)(sA + (i0+1)*AS + 2*pj);
            const float as0 = A0.x + A0.y;
            const float as1 = A1.x + A1.y;
            const int r = (phi - (pj >> 3) + 7)*15 + (pwi - (pj & 7) + 7);
            const float4 v0a = *(const float4*)(sV + (2*pj)*QS + c0);
            const float4 v0b = *(const float4*)(sV + (2*pj)*QS + c0 + 4);
            const float4 v1a = *(const float4*)(sV + (2*pj+1)*QS + c0);
            const float4 v1b = *(const float4*)(sV + (2*pj+1)*QS + c0 + 4);
            const float4 vea = *(const float4*)(sVE + r*QS + c0);
            const float4 veb = *(const float4*)(sVE + r*QS + c0 + 4);

            acc0a.x += A0.x*v0a.x + A0.y*v1a.x + as0*vea.x;
            acc0a.y += A0.x*v0a.y + A0.y*v1a.y + as0*vea.y;
            acc0a.z += A0.x*v0a.z + A0.y*v1a.z + as0*vea.z;
            acc0a.w += A0.x*v0a.w + A0.y*v1a.w + as0*vea.w;
            acc0b.x += A0.x*v0b.x + A0.y*v1b.x + as0*veb.x;
            acc0b.y += A0.x*v0b.y + A0.y*v1b.y + as0*veb.y;
            acc0b.z += A0.x*v0b.z + A0.y*v1b.z + as0*veb.z;
            acc0b.w += A0.x*v0b.w + A0.y*v1b.w + as0*veb.w;

            acc1a.x += A1.x*v0a.x + A1.y*v1a.x + as1*vea.x;
            acc1a.y += A1.x*v0a.y + A1.y*v1a.y + as1*vea.y;
            acc1a.z += A1.x*v0a.z + A1.y*v1a.z + as1*vea.z;
            acc1a.w += A1.x*v0a.w + A1.y*v1a.w + as1*vea.w;
            acc1b.x += A1.x*v0b.x + A1.y*v1b.x + as1*veb.x;
            acc1b.y += A1.x*v0b.y + A1.y*v1b.y + as1*veb.y;
            acc1b.z += A1.x*v0b.z + A1.y*v1b.z + as1*veb.z;
            acc1b.w += A1.x*v0b.w + A1.y*v1b.w + as1*veb.w;
        }

        const int wh = p >> 3, ww = p & 7;
        const int gy = (wi*8 + wh + SHIFT) & 127;
        const int gx = (wj*8 + ww + SHIFT) & 127;
        float* o0 = out + (size_t)(((b*128 + gy)*128 + gx)*2*128) + h*32 + c0;       // n=0
        float* o1 = o0 + 128;                                                         // n=1
        *(float4*)o0       = acc0a;
        *(float4*)(o0 + 4) = acc0b;
        *(float4*)o1       = acc1a;
        *(float4*)(o1 + 4) = acc1b;
    }
}

extern "C" void kernel_launch(void* const* d_in, const int* in_sizes, int n_in,
                              void* d_out, int out_size)
{
    const float* qkv  = (const float*)d_in[0];
    const float* mask = (const float*)d_in[1];
    const float* rpe  = (const float*)d_in[2];
    // d_in[3] (rel_pos_index) recomputed on the fly in-kernel

    const size_t smem = SMEM_FLOATS * sizeof(float);
    cudaFuncSetAttribute(swin_attn_kernel,
                         cudaFuncAttributeMaxDynamicSharedMemorySize, (int)smem);
    dim3 grid(1024, HEADS);
    swin_attn_kernel<<<grid, 256, smem>>>(qkv, mask, rpe, (float*)d_out);
}